// round 12
// baseline (speedup 1.0000x reference)
#include <cuda_runtime.h>

#define NEG (-1e30f)

constexpr int Bz = 8, IMG = 224, G = 14;
constexpr int N = 196, D = 128, NP = 208;
constexpr int R = Bz * NP;          // 1664 padded rows
constexpr int RB2 = R / 2;          // 832 row blocks

// ---------------- scratch (device globals; zero-init, no allocation) ----------------
__device__ float  g_x[R * D];
__device__ float  g_q[R * D];
__device__ float  g_s[R * 256];
__device__ float  g_h1[R * 256];
__device__ float4 g_k4[Bz * 32 * NP];     // [b][e4][j]
__device__ float4 g_vt4[Bz * 64 * 128];   // [b][j4][d]; j4>=49 stays 0
__device__ float  g_pooled[Bz * D];
__device__ float4 g_wt[97536];            // transposed weights, k4-major

// host-only offsets (float4 units), passed as kernel args
constexpr int OFF_Q[2]  = {8192, 36864};
constexpr int OFF_K[2]  = {12288, 40960};
constexpr int OFF_V[2]  = {16384, 45056};
constexpr int OFF_F1[2] = {20480, 49152};
constexpr int OFF_F2[2] = {28672, 57344};
constexpr int OFF_HEAD  = 65536;

__device__ __forceinline__ void trop4(float& a, float4 xv, float4 wv) {
  a = fmaxf(a, xv.x + wv.x);
  a = fmaxf(a, xv.y + wv.y);
  a = fmaxf(a, xv.z + wv.z);
  a = fmaxf(a, xv.w + wv.w);
}

// ---------------- double-buffered tropical mat-max core ----------------
// acc[NR] over NK4 float4 k-steps. W elem: Wt[k4*WS + c]. x elem: xs4[r*XSTR + k4].
template <int NK4, int NR, int WS, int XSTR>
__device__ __forceinline__ void trop_mm4(const float4* __restrict__ Wt, int c,
                                         const float4* xs4, float* acc) {
  constexpr int NG = NK4 / 4;
  float4 wreg[2][4];
  #pragma unroll
  for (int u = 0; u < 4; u++) wreg[0][u] = Wt[u * WS + c];
  #pragma unroll
  for (int g = 0; g < NG; g++) {
    if (g + 1 < NG) {
      #pragma unroll
      for (int u = 0; u < 4; u++)
        wreg[(g + 1) & 1][u] = Wt[((g + 1) * 4 + u) * WS + c];
    }
    #pragma unroll
    for (int u = 0; u < 4; u++) {
      #pragma unroll
      for (int r = 0; r < NR; r++)
        trop4(acc[r], xs4[r * XSTR + g * 4 + u], wreg[g & 1][u]);
    }
  }
}

// ---------------- one-shot weight transpose into k4-major ----------------
struct SrcPtrs { const float* p[12]; };
__device__ const int c_cols[12] = {128, 128, 128, 128, 256, 128, 128, 128, 128, 256, 128, 1000};
__device__ const int c_Kd[12]   = {256, 128, 128, 128, 128, 256, 128, 128, 128, 128, 256, 128};
__device__ const int c_off[12]  = {0, 8192, 12288, 16384, 20480, 28672, 36864, 40960, 45056, 49152, 57344, 65536};

__global__ void k_trans(SrcPtrs sp) {
  int w = blockIdx.y;
  int cols = c_cols[w], K = c_Kd[w];
  int n4 = cols * (K >> 2);
  int idx = blockIdx.x * 256 + threadIdx.x;
  if (idx >= n4) return;
  int k4 = idx / cols, c = idx - k4 * cols;
  g_wt[c_off[w] + idx] = *(const float4*)(sp.p[w] + c * K + k4 * 4);
}

// ---------------- embed: patchify + trop_mm + pos (2 rows/block) ----------------
__global__ __launch_bounds__(128) void k_embed(const float* __restrict__ x,
                                               const float* __restrict__ pos) {
  __shared__ __align__(16) float xs[2 * 256];
  int tid = threadIdx.x, r0 = blockIdx.x * 2, b = r0 / NP;
  #pragma unroll
  for (int it = 0; it < 4; it++) {
    int idx = it * 128 + tid, rr = idx >> 8, j = idx & 255;
    int n = (r0 + rr) % NP; if (n > N - 1) n = N - 1;
    int gy = n / G, gx = n % G, py = j >> 4, px = j & 15;
    xs[idx] = x[(b * IMG + gy * 16 + py) * IMG + gx * 16 + px];
  }
  __syncthreads();
  float acc[2] = {NEG, NEG};
  trop_mm4<64, 2, 128, 64>(g_wt, tid, (const float4*)xs, acc);
  #pragma unroll
  for (int r = 0; r < 2; r++) {
    int rr = r0 + r, n = rr % NP; if (n > N - 1) n = N - 1;
    g_x[rr * D + tid] = acc[r] + pos[n * D + tid];
  }
}

// ---------------- QKV (y=0: q, y=1: k-rmx -> g_k4, y=2: v-rmx -> g_vt4) ----------------
__global__ __launch_bounds__(128) void k_qkv(int qoff, int koff, int voff) {
  __shared__ __align__(16) float xs[2 * 128];
  __shared__ float rmx[2];
  int tid = threadIdx.x, r0 = blockIdx.x * 2, y = blockIdx.y, b = r0 / NP;
  #pragma unroll
  for (int it = 0; it < 2; it++) xs[it * 128 + tid] = g_x[(r0 + it) * D + tid];
  __syncthreads();
  int w = tid >> 5, lane = tid & 31;
  if (w < 2) {                         // warp w reduces row w
    float m = fmaxf(fmaxf(xs[w * 128 + lane], xs[w * 128 + lane + 32]),
                    fmaxf(xs[w * 128 + lane + 64], xs[w * 128 + lane + 96]));
    #pragma unroll
    for (int o = 16; o; o >>= 1) m = fmaxf(m, __shfl_xor_sync(~0u, m, o));
    if (lane == 0) rmx[w] = m;
  }
  const float4* Wt = g_wt + (y == 0 ? qoff : (y == 1 ? koff : voff));
  float acc[2] = {NEG, NEG};
  trop_mm4<32, 2, 128, 32>(Wt, tid, (const float4*)xs, acc);
  __syncthreads();                     // publish rmx
  if (y == 0) {
    #pragma unroll
    for (int r = 0; r < 2; r++) g_q[(r0 + r) * D + tid] = acc[r];
  } else if (y == 1) {
    #pragma unroll
    for (int r = 0; r < 2; r++) {
      int n = (r0 + r) % NP;
      ((float*)g_k4)[((b * 32 + (tid >> 2)) * NP + n) * 4 + (tid & 3)] = acc[r] - rmx[r];
    }
  } else {
    #pragma unroll
    for (int r = 0; r < 2; r++) {
      int n = (r0 + r) % NP;
      ((float*)g_vt4)[((b * 64 + (n >> 2)) * 128 + tid) * 4 + (n & 3)] = acc[r] - rmx[r];
    }
  }
}

// ---------------- scores: S[i][j] = max_e(q[i][e] + k'[j][e]); j>=196 -> NEG ----------------
__global__ __launch_bounds__(128) void k_score() {
  __shared__ __align__(16) float xs[2 * 128];
  int tid = threadIdx.x, r0 = blockIdx.x * 2, j = blockIdx.y * 128 + tid;
  int b = r0 / NP;
  #pragma unroll
  for (int it = 0; it < 2; it++) xs[it * 128 + tid] = g_q[(r0 + it) * D + tid];
  __syncthreads();
  float acc[2] = {NEG, NEG};
  if (j < N)
    trop_mm4<32, 2, NP, 32>(g_k4 + b * 32 * NP, j, (const float4*)xs, acc);
  g_s[(r0 + 0) * 256 + j] = acc[0];
  g_s[(r0 + 1) * 256 + j] = acc[1];
}

// ---------------- FF1: h = max(trop(x,W1) - rmx, tau) ----------------
__global__ __launch_bounds__(128) void k_ff1(int f1off, const float* __restrict__ tau) {
  __shared__ __align__(16) float xs[2 * 128];
  __shared__ float rmx[2];
  int tid = threadIdx.x, r0 = blockIdx.x * 2, c = blockIdx.y * 128 + tid;
  #pragma unroll
  for (int it = 0; it < 2; it++) xs[it * 128 + tid] = g_x[(r0 + it) * D + tid];
  __syncthreads();
  int w = tid >> 5, lane = tid & 31;
  if (w < 2) {
    float m = fmaxf(fmaxf(xs[w * 128 + lane], xs[w * 128 + lane + 32]),
                    fmaxf(xs[w * 128 + lane + 64], xs[w * 128 + lane + 96]));
    #pragma unroll
    for (int o = 16; o; o >>= 1) m = fmaxf(m, __shfl_xor_sync(~0u, m, o));
    if (lane == 0) rmx[w] = m;
  }
  float acc[2] = {NEG, NEG};
  trop_mm4<32, 2, 256, 32>(g_wt + f1off, c, (const float4*)xs, acc);
  __syncthreads();                     // publish rmx
  float tv = __ldg(tau);
  #pragma unroll
  for (int r = 0; r < 2; r++)
    g_h1[(r0 + r) * 256 + c] = fmaxf(acc[r] - rmx[r], tv);
}

// ---------------- out: o = trop(src, W); x = max(x, o - rowmax_d(o)) ----------------
// ATT: src=g_s, W=g_vt4 per batch.  else: src=g_h1, W=g_wt+wtoff.
template <int NK4, bool ATT>
__global__ __launch_bounds__(128) void k_out(int wtoff) {
  __shared__ __align__(16) float xs[2 * 256];
  __shared__ float part[2][4];
  int tid = threadIdx.x, r0 = blockIdx.x * 2, b = r0 / NP;
  const float* src = ATT ? (const float*)g_s : (const float*)g_h1;
  #pragma unroll
  for (int it = 0; it < 4; it++) xs[it * 128 + tid] = src[r0 * 256 + it * 128 + tid];
  __syncthreads();
  const float4* Wt = ATT ? (g_vt4 + b * 64 * 128) : (g_wt + wtoff);
  float acc[2] = {NEG, NEG};
  trop_mm4<NK4, 2, 128, 64>(Wt, tid, (const float4*)xs, acc);
  int w = tid >> 5, lane = tid & 31;
  #pragma unroll
  for (int r = 0; r < 2; r++) {
    float v = acc[r];
    #pragma unroll
    for (int o = 16; o; o >>= 1) v = fmaxf(v, __shfl_xor_sync(~0u, v, o));
    if (lane == 0) part[r][w] = v;
  }
  __syncthreads();
  #pragma unroll
  for (int r = 0; r < 2; r++) {
    float rm = fmaxf(fmaxf(part[r][0], part[r][1]), fmaxf(part[r][2], part[r][3]));
    int o_ = (r0 + r) * D + tid;
    g_x[o_] = fmaxf(g_x[o_], acc[r] - rm);
  }
}

// ---------------- pool + head ----------------
__global__ void k_pool() {
  __shared__ float pp[4][128];
  int b = blockIdx.x, tid = threadIdx.x, d = tid & 127, gp = tid >> 7;
  float m = NEG;
  for (int n = gp; n < N; n += 4) m = fmaxf(m, g_x[(b * NP + n) * D + d]);
  pp[gp][d] = m;
  __syncthreads();
  if (gp == 0)
    g_pooled[b * D + d] = fmaxf(fmaxf(pp[0][d], pp[1][d]), fmaxf(pp[2][d], pp[3][d]));
}

__global__ __launch_bounds__(128) void k_head(int hoff, const float* __restrict__ ls,
                                              float* __restrict__ out) {
  __shared__ __align__(16) float ps[128];
  int b = blockIdx.y, tid = threadIdx.x, c = blockIdx.x * 128 + tid;
  ps[tid] = g_pooled[b * D + tid];
  __syncthreads();
  if (c < 1000) {
    float a = NEG;
    trop_mm4<32, 1, 1000, 1>(g_wt + hoff, c, (const float4*)ps, &a);
    out[b * 1000 + c] = a * __ldg(ls);
  }
}

// ---------------- launch ----------------
extern "C" void kernel_launch(void* const* d_in, const int* in_sizes, int n_in,
                              void* d_out, int out_size) {
  const float* x      = (const float*)d_in[0];
  const float* pos    = (const float*)d_in[2];
  const float* tau[2] = {(const float*)d_in[8], (const float*)d_in[14]};
  const float* lscale = (const float*)d_in[16];
  float* out = (float*)d_out;

  SrcPtrs sp = {{(const float*)d_in[1],
                 (const float*)d_in[3], (const float*)d_in[4], (const float*)d_in[5],
                 (const float*)d_in[6], (const float*)d_in[7],
                 (const float*)d_in[9], (const float*)d_in[10], (const float*)d_in[11],
                 (const float*)d_in[12], (const float*)d_in[13],
                 (const float*)d_in[15]}};

  k_trans<<<dim3(125, 12), 256>>>(sp);
  k_embed<<<RB2, 128>>>(x, pos);
  for (int l = 0; l < 2; l++) {
    k_qkv<<<dim3(RB2, 3), 128>>>(OFF_Q[l], OFF_K[l], OFF_V[l]);
    k_score<<<dim3(RB2, 2), 128>>>();
    k_out<52, true><<<RB2, 128>>>(0);          // attention out + pnorm + residual
    k_ff1<<<dim3(RB2, 2), 128>>>(OFF_F1[l], tau[l]);
    k_out<64, false><<<RB2, 128>>>(OFF_F2[l]); // FF2 + pnorm + residual
  }
  k_pool<<<Bz, 512>>>();
  k_head<<<dim3(8, Bz), 128>>>(OFF_HEAD, lscale, out);
}

// round 13
// speedup vs baseline: 1.4547x; 1.4547x over previous
#include <cuda_runtime.h>

#define NEG (-1e30f)

constexpr int Bz = 8, IMG = 224, G = 14;
constexpr int N = 196, D = 128, NP = 208;
constexpr int R = Bz * NP;          // 1664 padded rows
constexpr int RB4 = R / 4;          // 416 row blocks

// ---------------- scratch (device globals; zero-init, no allocation) ----------------
__device__ float  g_x[R * D];
__device__ float  g_q[R * D];
__device__ float  g_s[R * 256];
__device__ float  g_h1[R * 256];
__device__ float4 g_k4[Bz * 32 * NP];     // [b][e4][j]
__device__ float4 g_vt4[Bz * 64 * 128];   // [b][j4][d]; j4>=49 stays 0
__device__ float  g_pooled[Bz * D];
__device__ float4 g_wt[97536];            // transposed weights, k4-major

// host-only offsets (float4 units), passed as kernel args
constexpr int OFF_Q[2]  = {8192, 36864};
constexpr int OFF_K[2]  = {12288, 40960};
constexpr int OFF_V[2]  = {16384, 45056};
constexpr int OFF_F1[2] = {20480, 49152};
constexpr int OFF_F2[2] = {28672, 57344};
constexpr int OFF_HEAD  = 65536;

// tree-form: only ONE serial fmax on the accumulator per k4 (dep chain 4x shorter)
__device__ __forceinline__ void trop4(float& a, float4 xv, float4 wv) {
  float t0 = fmaxf(xv.x + wv.x, xv.y + wv.y);
  float t1 = fmaxf(xv.z + wv.z, xv.w + wv.w);
  a = fmaxf(a, fmaxf(t0, t1));
}

// ---------------- distance-2 prefetch tropical mat-max core ----------------
// acc[NR] over NK4 float4 k-steps. W elem: Wt[k4*WS + c]. x elem: xs4[r*XSTR + k4].
// 3 rotating W buffers; group g+2's 4 LDG.128 issued before group g's math.
template <int NK4, int NR, int WS, int XSTR>
__device__ __forceinline__ void trop_mm4(const float4* __restrict__ Wt, int c,
                                         const float4* xs4, float* acc) {
  constexpr int NG = NK4 / 4;
  float4 wreg[3][4];
  #pragma unroll
  for (int u = 0; u < 4; u++) wreg[0][u] = Wt[u * WS + c];
  if (NG > 1) {
    #pragma unroll
    for (int u = 0; u < 4; u++) wreg[1][u] = Wt[(4 + u) * WS + c];
  }
  #pragma unroll
  for (int g = 0; g < NG; g++) {
    if (g + 2 < NG) {
      #pragma unroll
      for (int u = 0; u < 4; u++)
        wreg[(g + 2) % 3][u] = Wt[((g + 2) * 4 + u) * WS + c];
    }
    #pragma unroll
    for (int u = 0; u < 4; u++) {
      #pragma unroll
      for (int r = 0; r < NR; r++)
        trop4(acc[r], xs4[r * XSTR + g * 4 + u], wreg[g % 3][u]);
    }
  }
}

// ---------------- one-shot weight transpose into k4-major ----------------
struct SrcPtrs { const float* p[12]; };
__device__ const int c_cols[12] = {128, 128, 128, 128, 256, 128, 128, 128, 128, 256, 128, 1000};
__device__ const int c_Kd[12]   = {256, 128, 128, 128, 128, 256, 128, 128, 128, 128, 256, 128};
__device__ const int c_off[12]  = {0, 8192, 12288, 16384, 20480, 28672, 36864, 40960, 45056, 49152, 57344, 65536};

__global__ void k_trans(SrcPtrs sp) {
  int w = blockIdx.y;
  int cols = c_cols[w], K = c_Kd[w];
  int n4 = cols * (K >> 2);
  int idx = blockIdx.x * 256 + threadIdx.x;
  if (idx >= n4) return;
  int k4 = idx / cols, c = idx - k4 * cols;
  g_wt[c_off[w] + idx] = *(const float4*)(sp.p[w] + c * K + k4 * 4);
}

// ---------------- embed: patchify + trop_mm + pos ----------------
__global__ __launch_bounds__(128) void k_embed(const float* __restrict__ x,
                                               const float* __restrict__ pos) {
  __shared__ __align__(16) float xs[4 * 256];
  int tid = threadIdx.x, r0 = blockIdx.x * 4, b = r0 / NP;
  #pragma unroll
  for (int it = 0; it < 8; it++) {
    int idx = it * 128 + tid, rr = idx >> 8, j = idx & 255;
    int n = (r0 + rr) % NP; if (n > N - 1) n = N - 1;
    int gy = n / G, gx = n % G, py = j >> 4, px = j & 15;
    xs[idx] = x[(b * IMG + gy * 16 + py) * IMG + gx * 16 + px];
  }
  __syncthreads();
  float acc[4] = {NEG, NEG, NEG, NEG};
  trop_mm4<64, 4, 128, 64>(g_wt, tid, (const float4*)xs, acc);
  #pragma unroll
  for (int r = 0; r < 4; r++) {
    int rr = r0 + r, n = rr % NP; if (n > N - 1) n = N - 1;
    g_x[rr * D + tid] = acc[r] + pos[n * D + tid];
  }
}

// ---------------- QKV (y=0: q, y=1: k-rmx -> g_k4, y=2: v-rmx -> g_vt4) ----------------
__global__ __launch_bounds__(128) void k_qkv(int qoff, int koff, int voff) {
  __shared__ __align__(16) float xs[4 * 128];
  __shared__ float rmx[4];
  int tid = threadIdx.x, r0 = blockIdx.x * 4, y = blockIdx.y, b = r0 / NP;
  #pragma unroll
  for (int it = 0; it < 4; it++) xs[it * 128 + tid] = g_x[(r0 + it) * D + tid];
  __syncthreads();
  {
    int w = tid >> 5, lane = tid & 31;   // warp w owns row w
    float m = fmaxf(fmaxf(xs[w * 128 + lane], xs[w * 128 + lane + 32]),
                    fmaxf(xs[w * 128 + lane + 64], xs[w * 128 + lane + 96]));
    #pragma unroll
    for (int o = 16; o; o >>= 1) m = fmaxf(m, __shfl_xor_sync(~0u, m, o));
    if (lane == 0) rmx[w] = m;
  }
  const float4* Wt = g_wt + (y == 0 ? qoff : (y == 1 ? koff : voff));
  float acc[4] = {NEG, NEG, NEG, NEG};
  trop_mm4<32, 4, 128, 32>(Wt, tid, (const float4*)xs, acc);
  __syncthreads();                                     // publish rmx
  if (y == 0) {
    #pragma unroll
    for (int r = 0; r < 4; r++) g_q[(r0 + r) * D + tid] = acc[r];
  } else if (y == 1) {
    #pragma unroll
    for (int r = 0; r < 4; r++) {
      int n = (r0 + r) % NP;
      ((float*)g_k4)[((b * 32 + (tid >> 2)) * NP + n) * 4 + (tid & 3)] = acc[r] - rmx[r];
    }
  } else {
    #pragma unroll
    for (int r = 0; r < 4; r++) {
      int n = (r0 + r) % NP;
      ((float*)g_vt4)[((b * 64 + (n >> 2)) * 128 + tid) * 4 + (n & 3)] = acc[r] - rmx[r];
    }
  }
}

// ---------------- scores: S[i][j] = max_e(q[i][e] + k'[j][e]); j>=196 -> NEG ----------------
__global__ __launch_bounds__(128) void k_score() {
  __shared__ __align__(16) float xs[4 * 128];
  int tid = threadIdx.x, r0 = blockIdx.x * 4, j = blockIdx.y * 128 + tid;
  int b = r0 / NP;
  #pragma unroll
  for (int it = 0; it < 4; it++) xs[it * 128 + tid] = g_q[(r0 + it) * D + tid];
  __syncthreads();
  float acc[4] = {NEG, NEG, NEG, NEG};
  if (j < N)
    trop_mm4<32, 4, NP, 32>(g_k4 + b * 32 * NP, j, (const float4*)xs, acc);
  #pragma unroll
  for (int r = 0; r < 4; r++) g_s[(r0 + r) * 256 + j] = acc[r];
}

// ---------------- FF1: h = max(trop(x,W1) - rmx, tau) ----------------
__global__ __launch_bounds__(128) void k_ff1(int f1off, const float* __restrict__ tau) {
  __shared__ __align__(16) float xs[4 * 128];
  __shared__ float rmx[4];
  int tid = threadIdx.x, r0 = blockIdx.x * 4, c = blockIdx.y * 128 + tid;
  #pragma unroll
  for (int it = 0; it < 4; it++) xs[it * 128 + tid] = g_x[(r0 + it) * D + tid];
  __syncthreads();
  {
    int w = tid >> 5, lane = tid & 31;
    float m = fmaxf(fmaxf(xs[w * 128 + lane], xs[w * 128 + lane + 32]),
                    fmaxf(xs[w * 128 + lane + 64], xs[w * 128 + lane + 96]));
    #pragma unroll
    for (int o = 16; o; o >>= 1) m = fmaxf(m, __shfl_xor_sync(~0u, m, o));
    if (lane == 0) rmx[w] = m;
  }
  float acc[4] = {NEG, NEG, NEG, NEG};
  trop_mm4<32, 4, 256, 32>(g_wt + f1off, c, (const float4*)xs, acc);
  __syncthreads();                                     // publish rmx
  float tv = __ldg(tau);
  #pragma unroll
  for (int r = 0; r < 4; r++)
    g_h1[(r0 + r) * 256 + c] = fmaxf(acc[r] - rmx[r], tv);
}

// ---------------- out: o = trop(src, W); x = max(x, o - rowmax_d(o)) ----------------
// ATT: src=g_s, W=g_vt4 per batch.  else: src=g_h1, W=g_wt+wtoff.
template <int NK4, bool ATT>
__global__ __launch_bounds__(128) void k_out(int wtoff) {
  __shared__ __align__(16) float xs[4 * 256];
  __shared__ float part[4][4];
  int tid = threadIdx.x, r0 = blockIdx.x * 4, b = r0 / NP;
  const float* src = ATT ? (const float*)g_s : (const float*)g_h1;
  #pragma unroll
  for (int it = 0; it < 8; it++) xs[it * 128 + tid] = src[r0 * 256 + it * 128 + tid];
  __syncthreads();
  const float4* Wt = ATT ? (g_vt4 + b * 64 * 128) : (g_wt + wtoff);
  float acc[4] = {NEG, NEG, NEG, NEG};
  trop_mm4<NK4, 4, 128, 64>(Wt, tid, (const float4*)xs, acc);
  int w = tid >> 5, lane = tid & 31;
  #pragma unroll
  for (int r = 0; r < 4; r++) {
    float v = acc[r];
    #pragma unroll
    for (int o = 16; o; o >>= 1) v = fmaxf(v, __shfl_xor_sync(~0u, v, o));
    if (lane == 0) part[r][w] = v;
  }
  __syncthreads();
  #pragma unroll
  for (int r = 0; r < 4; r++) {
    float rm = fmaxf(fmaxf(part[r][0], part[r][1]), fmaxf(part[r][2], part[r][3]));
    int o_ = (r0 + r) * D + tid;
    g_x[o_] = fmaxf(g_x[o_], acc[r] - rm);
  }
}

// ---------------- pool + head ----------------
__global__ void k_pool() {
  __shared__ float pp[4][128];
  int b = blockIdx.x, tid = threadIdx.x, d = tid & 127, gp = tid >> 7;
  float m = NEG;
  for (int n = gp; n < N; n += 4) m = fmaxf(m, g_x[(b * NP + n) * D + d]);
  pp[gp][d] = m;
  __syncthreads();
  if (gp == 0)
    g_pooled[b * D + d] = fmaxf(fmaxf(pp[0][d], pp[1][d]), fmaxf(pp[2][d], pp[3][d]));
}

__global__ __launch_bounds__(128) void k_head(int hoff, const float* __restrict__ ls,
                                              float* __restrict__ out) {
  __shared__ __align__(16) float ps[128];
  int b = blockIdx.y, tid = threadIdx.x, c = blockIdx.x * 128 + tid;
  ps[tid] = g_pooled[b * D + tid];
  __syncthreads();
  if (c < 1000) {
    float a = NEG;
    trop_mm4<32, 1, 1000, 1>(g_wt + hoff, c, (const float4*)ps, &a);
    out[b * 1000 + c] = a * __ldg(ls);
  }
}

// ---------------- launch ----------------
extern "C" void kernel_launch(void* const* d_in, const int* in_sizes, int n_in,
                              void* d_out, int out_size) {
  const float* x      = (const float*)d_in[0];
  const float* pos    = (const float*)d_in[2];
  const float* tau[2] = {(const float*)d_in[8], (const float*)d_in[14]};
  const float* lscale = (const float*)d_in[16];
  float* out = (float*)d_out;

  SrcPtrs sp = {{(const float*)d_in[1],
                 (const float*)d_in[3], (const float*)d_in[4], (const float*)d_in[5],
                 (const float*)d_in[6], (const float*)d_in[7],
                 (const float*)d_in[9], (const float*)d_in[10], (const float*)d_in[11],
                 (const float*)d_in[12], (const float*)d_in[13],
                 (const float*)d_in[15]}};

  k_trans<<<dim3(125, 12), 256>>>(sp);
  k_embed<<<RB4, 128>>>(x, pos);
  for (int l = 0; l < 2; l++) {
    k_qkv<<<dim3(RB4, 3), 128>>>(OFF_Q[l], OFF_K[l], OFF_V[l]);
    k_score<<<dim3(RB4, 2), 128>>>();
    k_out<52, true><<<RB4, 128>>>(0);          // attention out + pnorm + residual
    k_ff1<<<dim3(RB4, 2), 128>>>(OFF_F1[l], tau[l]);
    k_out<64, false><<<RB4, 128>>>(OFF_F2[l]); // FF2 + pnorm + residual
  }
  k_pool<<<Bz, 512>>>();
  k_head<<<dim3(8, Bz), 128>>>(OFF_HEAD, lscale, out);
}

// round 15
// speedup vs baseline: 1.6905x; 1.1621x over previous
#include <cuda_runtime.h>

#define NEG (-1e30f)

constexpr int Bz = 8, IMG = 224, G = 14;
constexpr int N = 196, D = 128, NP = 208;
constexpr int R = Bz * NP;          // 1664 padded rows
constexpr int RB4 = R / 4;          // 416 row blocks

// ---------------- scratch (device globals; zero-init, no allocation) ----------------
__device__ float  g_x[R * D];
__device__ float  g_q[R * D];
__device__ float  g_s[R * 256];
__device__ float  g_h1[R * 256];
__device__ float4 g_k4[Bz * 32 * NP];     // [b][e4][j]
__device__ float4 g_vt4[Bz * 64 * 128];   // [b][j4][d]; j4>=49 stays 0
__device__ float  g_pooled[Bz * D];
__device__ float4 g_wt[97536];            // transposed weights, k4-major

// host-only offsets (float4 units), passed as kernel args
constexpr int OFF_Q[2]  = {8192, 36864};
constexpr int OFF_K[2]  = {12288, 40960};
constexpr int OFF_V[2]  = {16384, 45056};
constexpr int OFF_F1[2] = {20480, 49152};
constexpr int OFF_F2[2] = {28672, 57344};
constexpr int OFF_HEAD  = 65536;

// serial accumulate form (R11-proven best)
__device__ __forceinline__ void trop4(float& a, float4 xv, float4 wv) {
  a = fmaxf(a, xv.x + wv.x);
  a = fmaxf(a, xv.y + wv.y);
  a = fmaxf(a, xv.z + wv.z);
  a = fmaxf(a, xv.w + wv.w);
}

// ---------------- double-buffered tropical mat-max core (R11 version) ----------------
// acc[NR] over NK4 float4 k-steps. W elem: Wt[k4*WS + c]. x elem: xs4[r*XSTR + k4].
template <int NK4, int NR, int WS, int XSTR>
__device__ __forceinline__ void trop_mm4(const float4* __restrict__ Wt, int c,
                                         const float4* xs4, float* acc) {
  constexpr int NG = NK4 / 4;
  float4 wreg[2][4];
  #pragma unroll
  for (int u = 0; u < 4; u++) wreg[0][u] = Wt[u * WS + c];
  #pragma unroll
  for (int g = 0; g < NG; g++) {
    if (g + 1 < NG) {
      #pragma unroll
      for (int u = 0; u < 4; u++)
        wreg[(g + 1) & 1][u] = Wt[((g + 1) * 4 + u) * WS + c];
    }
    #pragma unroll
    for (int u = 0; u < 4; u++) {
      #pragma unroll
      for (int r = 0; r < NR; r++)
        trop4(acc[r], xs4[r * XSTR + g * 4 + u], wreg[g & 1][u]);
    }
  }
}

// ---------------- one-shot weight transpose into k4-major ----------------
struct SrcPtrs { const float* p[12]; };
__device__ const int c_cols[12] = {128, 128, 128, 128, 256, 128, 128, 128, 128, 256, 128, 1000};
__device__ const int c_Kd[12]   = {256, 128, 128, 128, 128, 256, 128, 128, 128, 128, 256, 128};
__device__ const int c_off[12]  = {0, 8192, 12288, 16384, 20480, 28672, 36864, 40960, 45056, 49152, 57344, 65536};

__global__ void k_trans(SrcPtrs sp) {
  int w = blockIdx.y;
  int cols = c_cols[w], K = c_Kd[w];
  int n4 = cols * (K >> 2);
  int idx = blockIdx.x * 256 + threadIdx.x;
  if (idx >= n4) return;
  int k4 = idx / cols, c = idx - k4 * cols;
  g_wt[c_off[w] + idx] = *(const float4*)(sp.p[w] + c * K + k4 * 4);
}

// ---------------- embed: patchify + trop_mm + pos (split-K 256 thr) ----------------
__global__ __launch_bounds__(256) void k_embed(const float* __restrict__ x,
                                               const float* __restrict__ pos) {
  __shared__ __align__(16) float xs[4 * 256];
  __shared__ float comb[4][128];
  int tid = threadIdx.x, c = tid & 127, half = tid >> 7;
  int r0 = blockIdx.x * 4, b = r0 / NP;
  #pragma unroll
  for (int it = 0; it < 4; it++) {
    int idx = it * 256 + tid, rr = idx >> 8, j = idx & 255;
    int n = (r0 + rr) % NP; if (n > N - 1) n = N - 1;
    int gy = n / G, gx = n % G, py = j >> 4, px = j & 15;
    xs[idx] = x[(b * IMG + gy * 16 + py) * IMG + gx * 16 + px];
  }
  __syncthreads();
  float acc[4] = {NEG, NEG, NEG, NEG};
  trop_mm4<32, 4, 128, 64>(g_wt + half * 32 * 128, c, (const float4*)xs + half * 32, acc);
  if (half) {
    #pragma unroll
    for (int r = 0; r < 4; r++) comb[r][c] = acc[r];
  }
  __syncthreads();
  if (!half) {
    #pragma unroll
    for (int r = 0; r < 4; r++) {
      float v = fmaxf(acc[r], comb[r][c]);
      int rr = r0 + r, n = rr % NP; if (n > N - 1) n = N - 1;
      g_x[rr * D + c] = v + pos[n * D + c];
    }
  }
}

// ---------------- QKV (split-K; y=0: q, y=1: k-rmx -> g_k4, y=2: v-rmx -> g_vt4) ----------------
__global__ __launch_bounds__(256) void k_qkv(int qoff, int koff, int voff) {
  __shared__ __align__(16) float xs[4 * 128];
  __shared__ float comb[4][128];
  __shared__ float rmx[4];
  int tid = threadIdx.x, c = tid & 127, half = tid >> 7;
  int r0 = blockIdx.x * 4, y = blockIdx.y, b = r0 / NP;
  #pragma unroll
  for (int it = 0; it < 2; it++) xs[it * 256 + tid] = g_x[r0 * D + it * 256 + tid];
  __syncthreads();
  {
    int w = tid >> 5, lane = tid & 31;   // warps 0-3 reduce rows 0-3
    if (w < 4) {
      float m = fmaxf(fmaxf(xs[w * 128 + lane], xs[w * 128 + lane + 32]),
                      fmaxf(xs[w * 128 + lane + 64], xs[w * 128 + lane + 96]));
      #pragma unroll
      for (int o = 16; o; o >>= 1) m = fmaxf(m, __shfl_xor_sync(~0u, m, o));
      if (lane == 0) rmx[w] = m;
    }
  }
  const float4* Wt = g_wt + (y == 0 ? qoff : (y == 1 ? koff : voff)) + half * 16 * 128;
  float acc[4] = {NEG, NEG, NEG, NEG};
  trop_mm4<16, 4, 128, 32>(Wt, c, (const float4*)xs + half * 16, acc);
  if (half) {
    #pragma unroll
    for (int r = 0; r < 4; r++) comb[r][c] = acc[r];
  }
  __syncthreads();                                     // combine + publish rmx
  if (!half) {
    #pragma unroll
    for (int r = 0; r < 4; r++) acc[r] = fmaxf(acc[r], comb[r][c]);
    if (y == 0) {
      #pragma unroll
      for (int r = 0; r < 4; r++) g_q[(r0 + r) * D + c] = acc[r];
    } else if (y == 1) {
      #pragma unroll
      for (int r = 0; r < 4; r++) {
        int n = (r0 + r) % NP;
        ((float*)g_k4)[((b * 32 + (c >> 2)) * NP + n) * 4 + (c & 3)] = acc[r] - rmx[r];
      }
    } else {
      #pragma unroll
      for (int r = 0; r < 4; r++) {
        int n = (r0 + r) % NP;
        ((float*)g_vt4)[((b * 64 + (n >> 2)) * 128 + c) * 4 + (n & 3)] = acc[r] - rmx[r];
      }
    }
  }
}

// ---------------- scores (split-K): S[i][j] = max_e(q[i][e] + k'[j][e]) ----------------
__global__ __launch_bounds__(256) void k_score() {
  __shared__ __align__(16) float xs[4 * 128];
  __shared__ float comb[4][128];
  int tid = threadIdx.x, c = tid & 127, half = tid >> 7;
  int r0 = blockIdx.x * 4, j = blockIdx.y * 128 + c, b = r0 / NP;
  #pragma unroll
  for (int it = 0; it < 2; it++) xs[it * 256 + tid] = g_q[r0 * D + it * 256 + tid];
  __syncthreads();
  float acc[4] = {NEG, NEG, NEG, NEG};
  if (j < N)
    trop_mm4<16, 4, NP, 32>(g_k4 + b * 32 * NP + half * 16 * NP, j,
                            (const float4*)xs + half * 16, acc);
  if (half) {
    #pragma unroll
    for (int r = 0; r < 4; r++) comb[r][c] = acc[r];
  }
  __syncthreads();
  if (!half) {
    #pragma unroll
    for (int r = 0; r < 4; r++) g_s[(r0 + r) * 256 + j] = fmaxf(acc[r], comb[r][c]);
  }
}

// ---------------- FF1 (split-K): h = max(trop(x,W1) - rmx, tau) ----------------
__global__ __launch_bounds__(256) void k_ff1(int f1off, const float* __restrict__ tau) {
  __shared__ __align__(16) float xs[4 * 128];
  __shared__ float comb[4][128];
  __shared__ float rmx[4];
  int tid = threadIdx.x, c = tid & 127, half = tid >> 7;
  int r0 = blockIdx.x * 4, col = blockIdx.y * 128 + c;
  #pragma unroll
  for (int it = 0; it < 2; it++) xs[it * 256 + tid] = g_x[r0 * D + it * 256 + tid];
  __syncthreads();
  {
    int w = tid >> 5, lane = tid & 31;
    if (w < 4) {
      float m = fmaxf(fmaxf(xs[w * 128 + lane], xs[w * 128 + lane + 32]),
                      fmaxf(xs[w * 128 + lane + 64], xs[w * 128 + lane + 96]));
      #pragma unroll
      for (int o = 16; o; o >>= 1) m = fmaxf(m, __shfl_xor_sync(~0u, m, o));
      if (lane == 0) rmx[w] = m;
    }
  }
  float acc[4] = {NEG, NEG, NEG, NEG};
  trop_mm4<16, 4, 256, 32>(g_wt + f1off + half * 16 * 256, col,
                           (const float4*)xs + half * 16, acc);
  if (half) {
    #pragma unroll
    for (int r = 0; r < 4; r++) comb[r][c] = acc[r];
  }
  __syncthreads();
  if (!half) {
    float tv = __ldg(tau);
    #pragma unroll
    for (int r = 0; r < 4; r++)
      g_h1[(r0 + r) * 256 + col] = fmaxf(fmaxf(acc[r], comb[r][c]) - rmx[r], tv);
  }
}

// ---------------- out (split-K): o = trop(src, W); x = max(x, o - rowmax_d(o)) ----------------
// ATT: src=g_s, W=g_vt4 per batch (2x26 k4).  else: src=g_h1, W=g_wt+wtoff (2x32 k4).
template <int NK4H, bool ATT>
__global__ __launch_bounds__(256) void k_out(int wtoff) {
  __shared__ __align__(16) float xs[4 * 256];
  __shared__ float comb[4][128];
  __shared__ float part[4][4];
  int tid = threadIdx.x, c = tid & 127, half = tid >> 7;
  int r0 = blockIdx.x * 4, b = r0 / NP;
  const float* src = ATT ? (const float*)g_s : (const float*)g_h1;
  #pragma unroll
  for (int it = 0; it < 4; it++) xs[it * 256 + tid] = src[r0 * 256 + it * 256 + tid];
  __syncthreads();
  const float4* Wt = (ATT ? (g_vt4 + b * 64 * 128) : (g_wt + wtoff)) + half * NK4H * 128;
  float acc[4] = {NEG, NEG, NEG, NEG};
  trop_mm4<NK4H, 4, 128, 64>(Wt, c, (const float4*)xs + half * NK4H, acc);
  if (half) {
    #pragma unroll
    for (int r = 0; r < 4; r++) comb[r][c] = acc[r];
  }
  __syncthreads();
  if (!half) {
    int w = tid >> 5, lane = tid & 31;
    #pragma unroll
    for (int r = 0; r < 4; r++) {
      acc[r] = fmaxf(acc[r], comb[r][c]);
      float v = acc[r];
      #pragma unroll
      for (int o = 16; o; o >>= 1) v = fmaxf(v, __shfl_xor_sync(~0u, v, o));
      if (lane == 0) part[r][w] = v;
    }
  }
  __syncthreads();
  if (!half) {
    #pragma unroll
    for (int r = 0; r < 4; r++) {
      float rm = fmaxf(fmaxf(part[r][0], part[r][1]), fmaxf(part[r][2], part[r][3]));
      int o_ = (r0 + r) * D + c;
      g_x[o_] = fmaxf(g_x[o_], acc[r] - rm);
    }
  }
}

// ---------------- pool + head ----------------
__global__ void k_pool() {
  __shared__ float pp[4][128];
  int b = blockIdx.x, tid = threadIdx.x, d = tid & 127, gp = tid >> 7;
  float m = NEG;
  for (int n = gp; n < N; n += 4) m = fmaxf(m, g_x[(b * NP + n) * D + d]);
  pp[gp][d] = m;
  __syncthreads();
  if (gp == 0)
    g_pooled[b * D + d] = fmaxf(fmaxf(pp[0][d], pp[1][d]), fmaxf(pp[2][d], pp[3][d]));
}

__global__ __launch_bounds__(128) void k_head(int hoff, const float* __restrict__ ls,
                                              float* __restrict__ out) {
  __shared__ __align__(16) float ps[128];
  int b = blockIdx.y, tid = threadIdx.x, c = blockIdx.x * 128 + tid;
  ps[tid] = g_pooled[b * D + tid];
  __syncthreads();
  if (c < 1000) {
    float a = NEG;
    trop_mm4<32, 1, 1000, 1>(g_wt + hoff, c, (const float4*)ps, &a);
    out[b * 1000 + c] = a * __ldg(ls);
  }
}

// ---------------- launch ----------------
extern "C" void kernel_launch(void* const* d_in, const int* in_sizes, int n_in,
                              void* d_out, int out_size) {
  const float* x      = (const float*)d_in[0];
  const float* pos    = (const float*)d_in[2];
  const float* tau[2] = {(const float*)d_in[8], (const float*)d_in[14]};
  const float* lscale = (const float*)d_in[16];
  float* out = (float*)d_out;

  SrcPtrs sp = {{(const float*)d_in[1],
                 (const float*)d_in[3], (const float*)d_in[4], (const float*)d_in[5],
                 (const float*)d_in[6], (const float*)d_in[7],
                 (const float*)d_in[9], (const float*)d_in[10], (const float*)d_in[11],
                 (const float*)d_in[12], (const float*)d_in[13],
                 (const float*)d_in[15]}};

  k_trans<<<dim3(125, 12), 256>>>(sp);
  k_embed<<<RB4, 256>>>(x, pos);
  for (int l = 0; l < 2; l++) {
    k_qkv<<<dim3(RB4, 3), 256>>>(OFF_Q[l], OFF_K[l], OFF_V[l]);
    k_score<<<dim3(RB4, 2), 256>>>();
    k_out<26, true><<<RB4, 256>>>(0);          // attention out + pnorm + residual
    k_ff1<<<dim3(RB4, 2), 256>>>(OFF_F1[l], tau[l]);
    k_out<32, false><<<RB4, 256>>>(OFF_F2[l]); // FF2 + pnorm + residual
  }
  k_pool<<<Bz, 512>>>();
  k_head<<<dim3(8, Bz), 128>>>(OFF_HEAD, lscale, out);
}

// round 16
// speedup vs baseline: 1.7339x; 1.0257x over previous
#include <cuda_runtime.h>

#define NEG (-1e30f)

constexpr int Bz = 8, IMG = 224, G = 14;
constexpr int N = 196, D = 128, NP = 208;
constexpr int R = Bz * NP;          // 1664 padded rows
constexpr int RB4 = R / 4;          // 416 row blocks

// ---------------- scratch (device globals; zero-init, no allocation) ----------------
__device__ float  g_x[R * D];
__device__ float  g_q[R * D];
__device__ float  g_s[R * 256];
__device__ float  g_h1[R * 256];
__device__ float4 g_k4[Bz * 32 * NP];     // [b][e4][j]
__device__ float4 g_vt4[Bz * 64 * 128];   // [b][j4][d]; j4>=49 stays 0
__device__ float  g_pooled[Bz * D];
__device__ float4 g_wt[97536];            // transposed weights, k4-major

// host-only offsets (float4 units), passed as kernel args
constexpr int OFF_Q[2]  = {8192, 36864};
constexpr int OFF_K[2]  = {12288, 40960};
constexpr int OFF_V[2]  = {16384, 45056};
constexpr int OFF_F1[2] = {20480, 49152};
constexpr int OFF_F2[2] = {28672, 57344};
constexpr int OFF_HEAD  = 65536;

// serial accumulate form (R11-proven best)
__device__ __forceinline__ void trop4(float& a, float4 xv, float4 wv) {
  a = fmaxf(a, xv.x + wv.x);
  a = fmaxf(a, xv.y + wv.y);
  a = fmaxf(a, xv.z + wv.z);
  a = fmaxf(a, xv.w + wv.w);
}

// ---------------- chunked-preload tropical mat-max core (CH=8, MLP=8) ----------------
// acc[NR] over NK4 float4 k-steps. W elem: Wt[k4*WS + c]. x elem: xs4[r*XSTR + k4].
template <int NK4, int NR, int WS, int XSTR>
__device__ __forceinline__ void trop_mm4(const float4* __restrict__ Wt, int c,
                                         const float4* xs4, float* acc) {
  constexpr int CH = 8;
  constexpr int NG = NK4 / CH;
  constexpr int REM = NK4 - NG * CH;
  #pragma unroll
  for (int g = 0; g < NG; g++) {
    float4 wv[CH];
    #pragma unroll
    for (int u = 0; u < CH; u++) wv[u] = Wt[(g * CH + u) * WS + c];
    #pragma unroll
    for (int u = 0; u < CH; u++) {
      #pragma unroll
      for (int r = 0; r < NR; r++)
        trop4(acc[r], xs4[r * XSTR + g * CH + u], wv[u]);
    }
  }
  if constexpr (REM > 0) {
    float4 wv[REM > 0 ? REM : 1];
    #pragma unroll
    for (int u = 0; u < REM; u++) wv[u] = Wt[(NG * CH + u) * WS + c];
    #pragma unroll
    for (int u = 0; u < REM; u++) {
      #pragma unroll
      for (int r = 0; r < NR; r++)
        trop4(acc[r], xs4[r * XSTR + NG * CH + u], wv[u]);
    }
  }
}

// ---------------- one-shot weight transpose into k4-major ----------------
struct SrcPtrs { const float* p[12]; };
__device__ const int c_cols[12] = {128, 128, 128, 128, 256, 128, 128, 128, 128, 256, 128, 1000};
__device__ const int c_Kd[12]   = {256, 128, 128, 128, 128, 256, 128, 128, 128, 128, 256, 128};
__device__ const int c_off[12]  = {0, 8192, 12288, 16384, 20480, 28672, 36864, 40960, 45056, 49152, 57344, 65536};

__global__ void k_trans(SrcPtrs sp) {
  int w = blockIdx.y;
  int cols = c_cols[w], K = c_Kd[w];
  int n4 = cols * (K >> 2);
  int idx = blockIdx.x * 256 + threadIdx.x;
  if (idx >= n4) return;
  int k4 = idx / cols, c = idx - k4 * cols;
  g_wt[c_off[w] + idx] = *(const float4*)(sp.p[w] + c * K + k4 * 4);
}

// ---------------- embed: patchify + trop_mm + pos (split-K 256 thr) ----------------
__global__ __launch_bounds__(256) void k_embed(const float* __restrict__ x,
                                               const float* __restrict__ pos) {
  __shared__ __align__(16) float xs[4 * 256];
  __shared__ float comb[4][128];
  int tid = threadIdx.x, c = tid & 127, half = tid >> 7;
  int r0 = blockIdx.x * 4, b = r0 / NP;
  #pragma unroll
  for (int it = 0; it < 4; it++) {
    int idx = it * 256 + tid, rr = idx >> 8, j = idx & 255;
    int n = (r0 + rr) % NP; if (n > N - 1) n = N - 1;
    int gy = n / G, gx = n % G, py = j >> 4, px = j & 15;
    xs[idx] = x[(b * IMG + gy * 16 + py) * IMG + gx * 16 + px];
  }
  __syncthreads();
  float acc[4] = {NEG, NEG, NEG, NEG};
  trop_mm4<32, 4, 128, 64>(g_wt + half * 32 * 128, c, (const float4*)xs + half * 32, acc);
  if (half) {
    #pragma unroll
    for (int r = 0; r < 4; r++) comb[r][c] = acc[r];
  }
  __syncthreads();
  if (!half) {
    #pragma unroll
    for (int r = 0; r < 4; r++) {
      float v = fmaxf(acc[r], comb[r][c]);
      int rr = r0 + r, n = rr % NP; if (n > N - 1) n = N - 1;
      g_x[rr * D + c] = v + pos[n * D + c];
    }
  }
}

// ---------------- QKV (split-K; y=0: q, y=1: k-rmx -> g_k4, y=2: v-rmx -> g_vt4) ----------------
__global__ __launch_bounds__(256) void k_qkv(int qoff, int koff, int voff) {
  __shared__ __align__(16) float xs[4 * 128];
  __shared__ float comb[4][128];
  __shared__ float rmx[4];
  int tid = threadIdx.x, c = tid & 127, half = tid >> 7;
  int r0 = blockIdx.x * 4, y = blockIdx.y, b = r0 / NP;
  #pragma unroll
  for (int it = 0; it < 2; it++) xs[it * 256 + tid] = g_x[r0 * D + it * 256 + tid];
  __syncthreads();
  {
    int w = tid >> 5, lane = tid & 31;   // warps 0-3 reduce rows 0-3
    if (w < 4) {
      float m = fmaxf(fmaxf(xs[w * 128 + lane], xs[w * 128 + lane + 32]),
                      fmaxf(xs[w * 128 + lane + 64], xs[w * 128 + lane + 96]));
      #pragma unroll
      for (int o = 16; o; o >>= 1) m = fmaxf(m, __shfl_xor_sync(~0u, m, o));
      if (lane == 0) rmx[w] = m;
    }
  }
  const float4* Wt = g_wt + (y == 0 ? qoff : (y == 1 ? koff : voff)) + half * 16 * 128;
  float acc[4] = {NEG, NEG, NEG, NEG};
  trop_mm4<16, 4, 128, 32>(Wt, c, (const float4*)xs + half * 16, acc);
  if (half) {
    #pragma unroll
    for (int r = 0; r < 4; r++) comb[r][c] = acc[r];
  }
  __syncthreads();                                     // combine + publish rmx
  if (!half) {
    #pragma unroll
    for (int r = 0; r < 4; r++) acc[r] = fmaxf(acc[r], comb[r][c]);
    if (y == 0) {
      #pragma unroll
      for (int r = 0; r < 4; r++) g_q[(r0 + r) * D + c] = acc[r];
    } else if (y == 1) {
      #pragma unroll
      for (int r = 0; r < 4; r++) {
        int n = (r0 + r) % NP;
        ((float*)g_k4)[((b * 32 + (c >> 2)) * NP + n) * 4 + (c & 3)] = acc[r] - rmx[r];
      }
    } else {
      #pragma unroll
      for (int r = 0; r < 4; r++) {
        int n = (r0 + r) % NP;
        ((float*)g_vt4)[((b * 64 + (n >> 2)) * 128 + c) * 4 + (n & 3)] = acc[r] - rmx[r];
      }
    }
  }
}

// ---------------- scores (split-K): S[i][j] = max_e(q[i][e] + k'[j][e]) ----------------
__global__ __launch_bounds__(256) void k_score() {
  __shared__ __align__(16) float xs[4 * 128];
  __shared__ float comb[4][128];
  int tid = threadIdx.x, c = tid & 127, half = tid >> 7;
  int r0 = blockIdx.x * 4, j = blockIdx.y * 128 + c, b = r0 / NP;
  #pragma unroll
  for (int it = 0; it < 2; it++) xs[it * 256 + tid] = g_q[r0 * D + it * 256 + tid];
  __syncthreads();
  float acc[4] = {NEG, NEG, NEG, NEG};
  if (j < N)
    trop_mm4<16, 4, NP, 32>(g_k4 + b * 32 * NP + half * 16 * NP, j,
                            (const float4*)xs + half * 16, acc);
  if (half) {
    #pragma unroll
    for (int r = 0; r < 4; r++) comb[r][c] = acc[r];
  }
  __syncthreads();
  if (!half) {
    #pragma unroll
    for (int r = 0; r < 4; r++) g_s[(r0 + r) * 256 + j] = fmaxf(acc[r], comb[r][c]);
  }
}

// ---------------- FF1 (split-K): h = max(trop(x,W1) - rmx, tau) ----------------
__global__ __launch_bounds__(256) void k_ff1(int f1off, const float* __restrict__ tau) {
  __shared__ __align__(16) float xs[4 * 128];
  __shared__ float comb[4][128];
  __shared__ float rmx[4];
  int tid = threadIdx.x, c = tid & 127, half = tid >> 7;
  int r0 = blockIdx.x * 4, col = blockIdx.y * 128 + c;
  #pragma unroll
  for (int it = 0; it < 2; it++) xs[it * 256 + tid] = g_x[r0 * D + it * 256 + tid];
  __syncthreads();
  {
    int w = tid >> 5, lane = tid & 31;
    if (w < 4) {
      float m = fmaxf(fmaxf(xs[w * 128 + lane], xs[w * 128 + lane + 32]),
                      fmaxf(xs[w * 128 + lane + 64], xs[w * 128 + lane + 96]));
      #pragma unroll
      for (int o = 16; o; o >>= 1) m = fmaxf(m, __shfl_xor_sync(~0u, m, o));
      if (lane == 0) rmx[w] = m;
    }
  }
  float acc[4] = {NEG, NEG, NEG, NEG};
  trop_mm4<16, 4, 256, 32>(g_wt + f1off + half * 16 * 256, col,
                           (const float4*)xs + half * 16, acc);
  if (half) {
    #pragma unroll
    for (int r = 0; r < 4; r++) comb[r][c] = acc[r];
  }
  __syncthreads();
  if (!half) {
    float tv = __ldg(tau);
    #pragma unroll
    for (int r = 0; r < 4; r++)
      g_h1[(r0 + r) * 256 + col] = fmaxf(fmaxf(acc[r], comb[r][c]) - rmx[r], tv);
  }
}

// ---------------- out (split-K): o = trop(src, W); x = max(x, o - rowmax_d(o)) ----------------
// ATT: src=g_s, W=g_vt4 per batch (2x26 k4).  else: src=g_h1, W=g_wt+wtoff (2x32 k4).
template <int NK4H, bool ATT>
__global__ __launch_bounds__(256) void k_out(int wtoff) {
  __shared__ __align__(16) float xs[4 * 256];
  __shared__ float comb[4][128];
  __shared__ float part[4][4];
  int tid = threadIdx.x, c = tid & 127, half = tid >> 7;
  int r0 = blockIdx.x * 4, b = r0 / NP;
  const float* src = ATT ? (const float*)g_s : (const float*)g_h1;
  #pragma unroll
  for (int it = 0; it < 4; it++) xs[it * 256 + tid] = src[r0 * 256 + it * 256 + tid];
  __syncthreads();
  const float4* Wt = (ATT ? (g_vt4 + b * 64 * 128) : (g_wt + wtoff)) + half * NK4H * 128;
  float acc[4] = {NEG, NEG, NEG, NEG};
  trop_mm4<NK4H, 4, 128, 64>(Wt, c, (const float4*)xs + half * NK4H, acc);
  if (half) {
    #pragma unroll
    for (int r = 0; r < 4; r++) comb[r][c] = acc[r];
  }
  __syncthreads();
  if (!half) {
    int w = tid >> 5, lane = tid & 31;
    #pragma unroll
    for (int r = 0; r < 4; r++) {
      acc[r] = fmaxf(acc[r], comb[r][c]);
      float v = acc[r];
      #pragma unroll
      for (int o = 16; o; o >>= 1) v = fmaxf(v, __shfl_xor_sync(~0u, v, o));
      if (lane == 0) part[r][w] = v;
    }
  }
  __syncthreads();
  if (!half) {
    #pragma unroll
    for (int r = 0; r < 4; r++) {
      float rm = fmaxf(fmaxf(part[r][0], part[r][1]), fmaxf(part[r][2], part[r][3]));
      int o_ = (r0 + r) * D + c;
      g_x[o_] = fmaxf(g_x[o_], acc[r] - rm);
    }
  }
}

// ---------------- pool + head ----------------
__global__ void k_pool() {
  __shared__ float pp[4][128];
  int b = blockIdx.x, tid = threadIdx.x, d = tid & 127, gp = tid >> 7;
  float m = NEG;
  for (int n = gp; n < N; n += 4) m = fmaxf(m, g_x[(b * NP + n) * D + d]);
  pp[gp][d] = m;
  __syncthreads();
  if (gp == 0)
    g_pooled[b * D + d] = fmaxf(fmaxf(pp[0][d], pp[1][d]), fmaxf(pp[2][d], pp[3][d]));
}

__global__ __launch_bounds__(128) void k_head(int hoff, const float* __restrict__ ls,
                                              float* __restrict__ out) {
  __shared__ __align__(16) float ps[128];
  int b = blockIdx.y, tid = threadIdx.x, c = blockIdx.x * 128 + tid;
  ps[tid] = g_pooled[b * D + tid];
  __syncthreads();
  if (c < 1000) {
    float a = NEG;
    trop_mm4<32, 1, 1000, 1>(g_wt + hoff, c, (const float4*)ps, &a);
    out[b * 1000 + c] = a * __ldg(ls);
  }
}

// ---------------- launch ----------------
extern "C" void kernel_launch(void* const* d_in, const int* in_sizes, int n_in,
                              void* d_out, int out_size) {
  const float* x      = (const float*)d_in[0];
  const float* pos    = (const float*)d_in[2];
  const float* tau[2] = {(const float*)d_in[8], (const float*)d_in[14]};
  const float* lscale = (const float*)d_in[16];
  float* out = (float*)d_out;

  SrcPtrs sp = {{(const float*)d_in[1],
                 (const float*)d_in[3], (const float*)d_in[4], (const float*)d_in[5],
                 (const float*)d_in[6], (const float*)d_in[7],
                 (const float*)d_in[9], (const float*)d_in[10], (const float*)d_in[11],
                 (const float*)d_in[12], (const float*)d_in[13],
                 (const float*)d_in[15]}};

  k_trans<<<dim3(125, 12), 256>>>(sp);
  k_embed<<<RB4, 256>>>(x, pos);
  for (int l = 0; l < 2; l++) {
    k_qkv<<<dim3(RB4, 3), 256>>>(OFF_Q[l], OFF_K[l], OFF_V[l]);
    k_score<<<dim3(RB4, 2), 256>>>();
    k_out<26, true><<<RB4, 256>>>(0);          // attention out + pnorm + residual
    k_ff1<<<dim3(RB4, 2), 256>>>(OFF_F1[l], tau[l]);
    k_out<32, false><<<RB4, 256>>>(OFF_F2[l]); // FF2 + pnorm + residual
  }
  k_pool<<<Bz, 512>>>();
  k_head<<<dim3(8, Bz), 128>>>(OFF_HEAD, lscale, out);
}